// round 6
// baseline (speedup 1.0000x reference)
#include <cuda_runtime.h>

#define HH 2048
#define WW 2048
#define MW 2047
#define NPIX (HH * WW)

#define CORE 64
#define B0   85
#define BP   88            // even pitch -> quad columns 8B-aligned
#define FAP  66
#define COP  42
#define NQ   41
#define NT   448
#define NSLOT 4
#define CO_DUMP (COP * COP)        // idle-slot dump cell
#define CO_SIZE (COP * COP + 48)   // covers dump reads + ST staging spill
#define ASIZE (B0 * BP)
#define SIO_IDLE (BP + 1)          // slot (a=1,b=1): odd offset like real slots
#define STP  88                    // STg staging pitch (87 rows)

__device__ __forceinline__ float2 lds2(const float* p) {
    return *reinterpret_cast<const float2*>(p);
}
__device__ __forceinline__ void sts2(float* p, float x, float y) {
    *reinterpret_cast<float2*>(p) = make_float2(x, y);
}

// ---------------------------------------------------------------------------
// One fused _compute iteration: unconditional compute, gated stores.
// All smem loads are even-aligned LDS.64 (conflict-free).
// ---------------------------------------------------------------------------
template <int K>
__device__ __forceinline__ void iter_step(
    const float* __restrict__ in, float* __restrict__ out,
    float* __restrict__ CO, float* __restrict__ FA,
    const int* sio, const int* sco, const int* sabm, float* fa,
    float w0, float w1, float w2, float w3, float w4,
    float w5, float w6, float w7, float w8,
    float alpha, float bs, float g)
{
    // Phase A: first conv at decimated corners (no predicates)
#pragma unroll
    for (int s = 0; s < NSLOT; ++s) {
        const float* p = in + sio[s];          // odd offset, col 2b-1
        const float2 q00 = lds2(p - 1);        // cols 2b-2,2b-1 (.y used)
        const float2 q01 = lds2(p + 1);        // cols 2b,2b+1
        const float2 q10 = lds2(p + BP - 1);
        const float2 q11 = lds2(p + BP + 1);
        const float2 q20 = lds2(p + 2 * BP - 1);
        const float2 q21 = lds2(p + 2 * BP + 1);
        float acc = fmaf(q00.y, w0, q01.x * w1);
        acc = fmaf(q01.y, w2, acc);
        acc = fmaf(q10.y, w3, acc);
        acc = fmaf(q11.x, w4, acc);
        acc = fmaf(q11.y, w5, acc);
        acc = fmaf(q20.y, w6, acc);
        acc = fmaf(q21.x, w7, acc);
        acc = fmaf(q21.y, w8, acc);
        CO[sco[s]] = acc;
    }
    __syncthreads();

    // Phase B: second conv from corners + laplacian + f accumulation
#pragma unroll
    for (int s = 0; s < NSLOT; ++s) {
        const float* p = in + sio[s];
        const float2 t0 = lds2(p + 1);                 // row 0: 2b,2b+1
        const float2 a1 = lds2(p + BP - 1);            // row 1: 2b-2,2b-1
        const float2 m1 = lds2(p + BP + 1);            //        2b,2b+1
        const float2 b1 = lds2(p + BP + 3);            //        2b+2,2b+3
        const float2 a2 = lds2(p + 2 * BP - 1);
        const float2 m2 = lds2(p + 2 * BP + 1);
        const float2 b2 = lds2(p + 2 * BP + 3);
        const float2 t3 = lds2(p + 3 * BP + 1);

        const float lap00 = 4.f * m1.x - a1.y - m1.y - t0.x - m2.x;
        const float lap01 = 4.f * m1.y - m1.x - b1.x - t0.y - m2.y;
        const float lap10 = 4.f * m2.x - a2.y - m2.y - m1.x - t3.x;
        const float lap11 = 4.f * m2.y - m2.x - b2.x - m1.y - t3.y;

        const float* co = CO + sco[s];
        const float o00 = co[0], o01 = co[1];
        const float o10 = co[COP], o11 = co[COP + 1];

        const float r00 = fmaf(alpha, o00 * w4, bs * lap00);
        const float r01 = fmaf(alpha, fmaf(o00, w5, o01 * w3), bs * lap01);
        const float r10 = fmaf(alpha, fmaf(o00, w7, o10 * w1), bs * lap10);
        const float r11 = fmaf(alpha,
            fmaf(o00, w8, fmaf(o01, w6, fmaf(o10, w2, o11 * w0))),
            bs * lap11);

        if (K < 5) {
            const int n = (sabm[s] >> 18) & 63;
            float* ob = out + sio[s] + BP + 1;
            if (n >= K) {                       // full interior quad (common)
                sts2(ob, r00, r01);
                sts2(ob + BP, r10, r11);
            } else {
                const int m = (sabm[s] >> 12) & 63;
                if (m >= K) {                   // partial edge quad (rare)
                    const int a = sabm[s] & 63, b = (sabm[s] >> 6) & 63;
                    const bool ch = (b <= 41 - K), rh = (a <= 41 - K);
                    ob[0] = r00;
                    if (ch) ob[1] = r01;
                    if (rh) { ob[BP] = r10; if (ch) ob[BP + 1] = r11; }
                }
            }
            // f accumulation: unpredicated (garbage gated at final store)
            fa[4 * s + 0] = fmaf(g, r00, fa[4 * s + 0]);
            fa[4 * s + 1] = fmaf(g, r01, fa[4 * s + 1]);
            fa[4 * s + 2] = fmaf(g, r10, fa[4 * s + 2]);
            fa[4 * s + 3] = fmaf(g, r11, fa[4 * s + 3]);
        } else {
            // K == 5: fold last term and store f to smem, gated by fm
            const int fm = (sabm[s] >> 24) & 15;
            if (fm) {
                const int a = sabm[s] & 63, b = (sabm[s] >> 6) & 63;
                float* fp = FA + (2 * a - 10) * FAP + (2 * b - 10);
                const float v00 = fmaf(g, r00, fa[4 * s + 0]);
                const float v01 = fmaf(g, r01, fa[4 * s + 1]);
                const float v10 = fmaf(g, r10, fa[4 * s + 2]);
                const float v11 = fmaf(g, r11, fa[4 * s + 3]);
                const bool r0ok = fm & 1, r1ok = fm & 2;
                const bool c0ok = fm & 4, c1ok = fm & 8;
                if (r0ok) {
                    if (c0ok && c1ok) sts2(fp, v00, v01);
                    else { if (c0ok) fp[0] = v00; if (c1ok) fp[1] = v01; }
                }
                if (r1ok) {
                    if (c0ok && c1ok) sts2(fp + FAP, v10, v11);
                    else { if (c0ok) fp[FAP] = v10; if (c1ok) fp[FAP + 1] = v11; }
                }
            }
        }
    }
    __syncthreads();
}

// ---------------------------------------------------------------------------
// Mega kernel: stage0 + 5 fused iterations + shrink epilogue, one launch.
// ---------------------------------------------------------------------------
__global__ __launch_bounds__(NT, 2) void mega_kernel(
    const float* __restrict__ STg, const float* __restrict__ dX,
    const float* __restrict__ dY, const float* __restrict__ bX,
    const float* __restrict__ bY, const float* __restrict__ alpha_p,
    const float* __restrict__ beta0_p, const float* __restrict__ beta1_p,
    const float* __restrict__ sigma_p, const float* __restrict__ gamma,
    const float* __restrict__ w9, float* __restrict__ out)
{
    extern __shared__ __align__(16) float sm[];
    float* A  = sm;                 // 85*88
    float* B  = A + ASIZE;          // 85*88
    float* CO = B + ASIZE;          // 42*42 + pad
    float* FA = B;                  // aliases B (dead after iter 4)
    float* ST = B;                  // STg staging 87x88 (spills into CO; both
                                    // dead until iter 1 phase A)

    const int tid = threadIdx.x;
    const int gx0 = blockIdx.x * CORE;
    const int gy0 = blockIdx.y * CORE;

    const float w0 = __ldg(&w9[0]), w1 = __ldg(&w9[1]), w2 = __ldg(&w9[2]);
    const float w3 = __ldg(&w9[3]), w4 = __ldg(&w9[4]), w5 = __ldg(&w9[5]);
    const float w6 = __ldg(&w9[6]), w7 = __ldg(&w9[7]), w8 = __ldg(&w9[8]);
    const float alpha = __ldg(alpha_p);
    const float sigma = __ldg(sigma_p);
    const float bs = __ldg(beta0_p) + sigma;

    const bool interior = (blockIdx.x >= 1) & (blockIdx.x <= gridDim.x - 2) &
                          (blockIdx.y >= 1) & (blockIdx.y <= gridDim.y - 2);

    // ===== stage0 (fused): build 85x85 base0 patch in A ====================
    // 1) stage STg patch (87x87, origin global (gy0-11, gx0-11)) into ST
    if (interior) {
        const float* src = STg + (gy0 - 11) * WW + (gx0 - 11);
        for (int idx = tid; idx < 87 * 87; idx += NT) {
            const int r = idx / 87;
            const int c = idx - r * 87;
            ST[r * STP + c] = __ldg(src + r * WW + c);
        }
    } else {
        for (int idx = tid; idx < 87 * 87; idx += NT) {
            const int r = idx / 87;
            const int c = idx - r * 87;
            ST[r * STP + c] = __ldg(&STg[((gy0 - 11 + r) & MW) * WW +
                                         ((gx0 - 11 + c) & MW)]);
        }
    }
    __syncthreads();

    // 2) base0 cell (r,c) = global (gy0-10+r, gx0-10+c):
    //    conv = corr(STg, flip(w)) from ST; se from direct global loads.
    if (interior) {
        for (int idx = tid; idx < B0 * B0; idx += NT) {
            const int r = idx / B0;
            const int c = idx - r * B0;
            const float* q = ST + r * STP + c;
            float conv = q[0] * w8;
            conv = fmaf(q[1], w7, conv);
            conv = fmaf(q[2], w6, conv);
            conv = fmaf(q[STP], w5, conv);
            conv = fmaf(q[STP + 1], w4, conv);
            conv = fmaf(q[STP + 2], w3, conv);
            conv = fmaf(q[2 * STP], w2, conv);
            conv = fmaf(q[2 * STP + 1], w1, conv);
            conv = fmaf(q[2 * STP + 2], w0, conv);
            const int ij = (gy0 - 10 + r) * WW + (gx0 - 10 + c);
            const float dxb_c = __ldg(&dX[ij]) - __ldg(&bX[ij]);
            const float dxb_l = __ldg(&dX[ij - 1]) - __ldg(&bX[ij - 1]);
            const float dyb_c = __ldg(&dY[ij]) - __ldg(&bY[ij]);
            const float dyb_u = __ldg(&dY[ij - WW]) - __ldg(&bY[ij - WW]);
            const float se = sigma * ((dxb_l - dxb_c) + (dyb_u - dyb_c));
            A[r * BP + c] = fmaf(alpha, conv, se);
        }
    } else {
        for (int idx = tid; idx < B0 * B0; idx += NT) {
            const int r = idx / B0;
            const int c = idx - r * B0;
            const float* q = ST + r * STP + c;
            float conv = q[0] * w8;
            conv = fmaf(q[1], w7, conv);
            conv = fmaf(q[2], w6, conv);
            conv = fmaf(q[STP], w5, conv);
            conv = fmaf(q[STP + 1], w4, conv);
            conv = fmaf(q[STP + 2], w3, conv);
            conv = fmaf(q[2 * STP], w2, conv);
            conv = fmaf(q[2 * STP + 1], w1, conv);
            conv = fmaf(q[2 * STP + 2], w0, conv);
            const int gi = (gy0 - 10 + r) & MW;
            const int gj = (gx0 - 10 + c) & MW;
            const int ij = gi * WW + gj;
            const int ijl = gi * WW + ((gj - 1) & MW);
            const int iju = ((gi - 1) & MW) * WW + gj;
            const float dxb_c = __ldg(&dX[ij]) - __ldg(&bX[ij]);
            const float dxb_l = __ldg(&dX[ijl]) - __ldg(&bX[ijl]);
            const float dyb_c = __ldg(&dY[ij]) - __ldg(&bY[ij]);
            const float dyb_u = __ldg(&dY[iju]) - __ldg(&bY[iju]);
            const float se = sigma * ((dxb_l - dxb_c) + (dyb_u - dyb_c));
            A[r * BP + c] = fmaf(alpha, conv, se);
        }
    }
    __syncthreads();

    // ===== fixed slot precompute ==========================================
    int sio[NSLOT], sco[NSLOT], sabm[NSLOT];
#pragma unroll
    for (int s = 0; s < NSLOT; ++s) {
        const int q = tid + s * NT;
        if (q < NQ * NQ) {
            const int a = q / NQ + 1;
            const int b = q - (a - 1) * NQ + 1;
            sio[s] = (2 * a - 1) * BP + (2 * b - 1);
            sco[s] = (a - 1) * COP + (b - 1);
            int m = min(min(a, b), min(42 - a, 42 - b));
            int n = min(min(a, b), min(41 - a, 41 - b));
            int fm = ((a >= 5 && a <= 37) ? 1 : 0) |
                     ((a >= 5 && a <= 36) ? 2 : 0) |
                     ((b >= 5 && b <= 37) ? 4 : 0) |
                     ((b >= 5 && b <= 36) ? 8 : 0);
            sabm[s] = a | (b << 6) | (m << 12) | (n << 18) | (fm << 24);
        } else {
            sio[s] = SIO_IDLE; sco[s] = CO_DUMP; sabm[s] = 0;
        }
    }

    // ===== f-reg init: fa = gamma[0] * base0 (quad values) ================
    float fa[4 * NSLOT];
    const float g0 = __ldg(&gamma[0]);
#pragma unroll
    for (int s = 0; s < NSLOT; ++s) {
        const float* p = A + sio[s] + BP + 1;   // pixel (2a, 2b)
        const float2 u = lds2(p);
        const float2 v = lds2(p + BP);
        fa[4 * s + 0] = g0 * u.x;
        fa[4 * s + 1] = g0 * u.y;
        fa[4 * s + 2] = g0 * v.x;
        fa[4 * s + 3] = g0 * v.y;
    }

    iter_step<1>(A, B, CO, FA, sio, sco, sabm, fa,
                 w0, w1, w2, w3, w4, w5, w6, w7, w8, alpha, bs, __ldg(&gamma[1]));
    iter_step<2>(B, A, CO, FA, sio, sco, sabm, fa,
                 w0, w1, w2, w3, w4, w5, w6, w7, w8, alpha, bs, __ldg(&gamma[2]));
    iter_step<3>(A, B, CO, FA, sio, sco, sabm, fa,
                 w0, w1, w2, w3, w4, w5, w6, w7, w8, alpha, bs, __ldg(&gamma[3]));
    iter_step<4>(B, A, CO, FA, sio, sco, sabm, fa,
                 w0, w1, w2, w3, w4, w5, w6, w7, w8, alpha, bs, __ldg(&gamma[4]));
    // iter 5 reads A; writes f directly into FA (=B, dead since iter-4 sync)
    iter_step<5>(A, B, CO, FA, sio, sco, sabm, fa,
                 w0, w1, w2, w3, w4, w5, w6, w7, w8, alpha, bs, __ldg(&gamma[5]));

    // ===== shrink / Bregman epilogue: 2 pixels per step ====================
    const float thr = __fdividef(__ldg(beta1_p), sigma);
    for (int idx = tid; idx < 64 * 32; idx += NT) {
        const int r = idx >> 5;
        const int cp = idx & 31;
        const float* fr0 = FA + r * FAP + 2 * cp;
        const float2 f0 = lds2(fr0);
        const float fR = fr0[2];
        const float2 f1 = lds2(fr0 + FAP);
        const float dxf0 = f0.y - f0.x, dxf1 = fR - f0.y;
        const float dyf0 = f1.x - f0.x, dyf1 = f1.y - f0.y;
        const int ij = (gy0 + r) * WW + gx0 + 2 * cp;
        const float2 bx = __ldg((const float2*)(bX + ij));
        const float2 by = __ldg((const float2*)(bY + ij));
        const float px0 = dxf0 + bx.x, py0 = dyf0 + by.x;
        const float px1 = dxf1 + bx.y, py1 = dyf1 + by.y;
        const float n0 = sqrtf(fmaf(px0, px0, py0 * py0));
        const float n1 = sqrtf(fmaf(px1, px1, py1 * py1));
        const float sh0 = __fdividef(fmaxf(n0 - thr, 0.f), n0 + 1e-8f);
        const float sh1 = __fdividef(fmaxf(n1 - thr, 0.f), n1 + 1e-8f);
        const float dxn0 = px0 * sh0, dyn0 = py0 * sh0;
        const float dxn1 = px1 * sh1, dyn1 = py1 * sh1;
        *(float2*)(out + ij) = f0;
        *(float2*)(out + NPIX + ij) = make_float2(dxn0, dxn1);
        *(float2*)(out + 2 * NPIX + ij) = make_float2(dyn0, dyn1);
        *(float2*)(out + 3 * NPIX + ij) =
            make_float2(bx.x + dxf0 - dxn0, bx.y + dxf1 - dxn1);
        *(float2*)(out + 4 * NPIX + ij) =
            make_float2(by.x + dyf0 - dyn0, by.y + dyf1 - dyn1);
    }
}

static const int SMEM_BYTES = (2 * ASIZE + CO_SIZE) * 4;

extern "C" void kernel_launch(void* const* d_in, const int* in_sizes, int n_in,
                              void* d_out, int out_size)
{
    const float* STg   = (const float*)d_in[0];
    const float* dX    = (const float*)d_in[1];
    const float* dY    = (const float*)d_in[2];
    const float* bX    = (const float*)d_in[3];
    const float* bY    = (const float*)d_in[4];
    const float* alpha = (const float*)d_in[7];
    const float* beta0 = (const float*)d_in[8];
    const float* beta1 = (const float*)d_in[9];
    const float* sigma = (const float*)d_in[10];
    const float* gamma = (const float*)d_in[11];
    const float* w9    = (const float*)d_in[12];

    float* out = (float*)d_out;

    cudaFuncSetAttribute(mega_kernel,
                         cudaFuncAttributeMaxDynamicSharedMemorySize,
                         SMEM_BYTES);
    dim3 g2(WW / CORE, HH / CORE);
    mega_kernel<<<g2, NT, SMEM_BYTES>>>(STg, dX, dY, bX, bY, alpha, beta0,
                                        beta1, sigma, gamma, w9, out);
}

// round 7
// speedup vs baseline: 1.2720x; 1.2720x over previous
#include <cuda_runtime.h>

#define HH 2048
#define WW 2048
#define MW 2047
#define NPIX (HH * WW)

#define CORE 64
#define B0   85
#define BP   88            // even pitch -> quad columns 8B-aligned
#define FAP  66
#define COP  42
#define NQ   41
#define NT   480
#define NRUN 451           // 11 a-runs x 41 b-cols
#define CO_DUMP (41 * COP)
#define CO_SIZE (48 * COP)
#define ASIZE (B0 * BP)
#define SIO_IDLE (BP + 1)  // run (a0=1,b=1) base: odd offset like real runs

__device__ float g_base0[NPIX];

__device__ __forceinline__ float2 lds2(const float* p) {
    return *reinterpret_cast<const float2*>(p);
}
__device__ __forceinline__ void sts2(float* p, float x, float y) {
    *reinterpret_cast<float2*>(p) = make_float2(x, y);
}

// ---------------------------------------------------------------------------
// Stage 0 (separate kernel, R5-proven): base0 = sigma*div + alpha*corr(STg,flip(w))
// ---------------------------------------------------------------------------
__global__ __launch_bounds__(256) void stage0_kernel(
    const float* __restrict__ STg, const float* __restrict__ dX,
    const float* __restrict__ dY, const float* __restrict__ bX,
    const float* __restrict__ bY, const float* __restrict__ alpha_p,
    const float* __restrict__ sigma_p, const float* __restrict__ w9,
    float* __restrict__ base)
{
    const int jp = blockIdx.x * 32 + threadIdx.x;
    const int j = 2 * jp;
    const int i = blockIdx.y * 8 + threadIdx.y;
    const float alpha = __ldg(alpha_p);
    const float sigma = __ldg(sigma_p);
    const int ij = i * WW + j;

    const bool border = (blockIdx.x == 0) | (blockIdx.x == gridDim.x - 1) |
                        (blockIdx.y == 0) | (blockIdx.y == gridDim.y - 1);

    if (!border) {
        const int um = ij - WW, dp = ij + WW;
        const float2 sC = __ldg((const float2*)(STg + ij));
        const float  sL = __ldg(&STg[ij - 1]),  sR = __ldg(&STg[ij + 2]);
        const float2 sU = __ldg((const float2*)(STg + um));
        const float  sUL = __ldg(&STg[um - 1]), sUR = __ldg(&STg[um + 2]);
        const float2 sD = __ldg((const float2*)(STg + dp));
        const float  sDL = __ldg(&STg[dp - 1]), sDR = __ldg(&STg[dp + 2]);

        const float w0 = __ldg(&w9[0]), w1 = __ldg(&w9[1]), w2 = __ldg(&w9[2]);
        const float w3 = __ldg(&w9[3]), w4 = __ldg(&w9[4]), w5 = __ldg(&w9[5]);
        const float w6 = __ldg(&w9[6]), w7 = __ldg(&w9[7]), w8 = __ldg(&w9[8]);

        float c0 = sUL * w8;
        c0 = fmaf(sU.x, w7, c0); c0 = fmaf(sU.y, w6, c0);
        c0 = fmaf(sL, w5, c0);   c0 = fmaf(sC.x, w4, c0);
        c0 = fmaf(sC.y, w3, c0); c0 = fmaf(sDL, w2, c0);
        c0 = fmaf(sD.x, w1, c0); c0 = fmaf(sD.y, w0, c0);

        float c1 = sU.x * w8;
        c1 = fmaf(sU.y, w7, c1); c1 = fmaf(sUR, w6, c1);
        c1 = fmaf(sC.x, w5, c1); c1 = fmaf(sC.y, w4, c1);
        c1 = fmaf(sR, w3, c1);   c1 = fmaf(sD.x, w2, c1);
        c1 = fmaf(sD.y, w1, c1); c1 = fmaf(sDR, w0, c1);

        const float2 dxC = __ldg((const float2*)(dX + ij));
        const float  dxL = __ldg(&dX[ij - 1]);
        const float2 bxC = __ldg((const float2*)(bX + ij));
        const float  bxL = __ldg(&bX[ij - 1]);
        const float2 dyC = __ldg((const float2*)(dY + ij));
        const float2 dyU = __ldg((const float2*)(dY + um));
        const float2 byC = __ldg((const float2*)(bY + ij));
        const float2 byU = __ldg((const float2*)(bY + um));

        const float dxb0 = dxC.x - bxC.x, dxb1 = dxC.y - bxC.y;
        const float dxbl0 = dxL - bxL;
        const float se0 = sigma * ((dxbl0 - dxb0) + ((dyU.x - byU.x) - (dyC.x - byC.x)));
        const float se1 = sigma * ((dxb0 - dxb1) + ((dyU.y - byU.y) - (dyC.y - byC.y)));

        *(float2*)(base + ij) = make_float2(fmaf(alpha, c0, se0),
                                            fmaf(alpha, c1, se1));
    } else {
#pragma unroll
        for (int t = 0; t < 2; ++t) {
            const int jj = j + t;
            const int idx = i * WW + jj;
            const int jm = (jj - 1) & MW, im = (i - 1) & MW;
            float dxb_c = __ldg(&dX[idx]) - __ldg(&bX[idx]);
            float dxb_l = __ldg(&dX[i * WW + jm]) - __ldg(&bX[i * WW + jm]);
            float dyb_c = __ldg(&dY[idx]) - __ldg(&bY[idx]);
            float dyb_u = __ldg(&dY[im * WW + jj]) - __ldg(&bY[im * WW + jj]);
            float se = sigma * ((dxb_l - dxb_c) + (dyb_u - dyb_c));
            float conv = 0.f;
#pragma unroll
            for (int p = 0; p < 3; ++p) {
                const int r = (i + p - 1) & MW;
#pragma unroll
                for (int q = 0; q < 3; ++q) {
                    const int c = (jj + q - 1) & MW;
                    conv = fmaf(__ldg(&STg[r * WW + c]),
                                __ldg(&w9[(2 - p) * 3 + (2 - q)]), conv);
                }
            }
            base[idx] = fmaf(alpha, conv, se);
        }
    }
}

// ---------------------------------------------------------------------------
// One fused _compute iteration: each thread owns a vertical run of 4 slots
// (a0..a0+3, same b). Rolling register windows share overlapping row loads.
// ---------------------------------------------------------------------------
template <int K>
__device__ __forceinline__ void iter_step(
    const float* __restrict__ in, float* __restrict__ out,
    float* __restrict__ CO, float* __restrict__ FA,
    int sio_base, int sco, const int* sabm, float* fa,
    float w0, float w1, float w2, float w3, float w4,
    float w5, float w6, float w7, float w8,
    float alpha, float bs, float g)
{
    // ---- Phase A: corners (a0..a0+3, b); consecutive windows share 1 row ---
    {
        const float* p = in + sio_base;
        float2 u0 = lds2(p - 1), u1 = lds2(p + 1);
#pragma unroll
        for (int k = 0; k < 4; ++k) {
            const float* q = p + (2 * k + 1) * BP;
            const float2 v0 = lds2(q - 1), v1 = lds2(q + 1);
            const float2 x0 = lds2(q + BP - 1), x1 = lds2(q + BP + 1);
            float acc = fmaf(u0.y, w0, u1.x * w1);
            acc = fmaf(u1.y, w2, acc);
            acc = fmaf(v0.y, w3, acc);
            acc = fmaf(v1.x, w4, acc);
            acc = fmaf(v1.y, w5, acc);
            acc = fmaf(x0.y, w6, acc);
            acc = fmaf(x1.x, w7, acc);
            acc = fmaf(x1.y, w8, acc);
            CO[sco + k * COP] = acc;
            u0 = x0; u1 = x1;
        }
    }
    __syncthreads();

    // ---- Phase B: quads (a0..a0+3, b); consecutive slots share 2 rows ------
    {
        const float* p = in + sio_base;
        float2 mT = lds2(p + 1);                               // row 0 (t0)
        float2 aL = lds2(p + BP - 1);                          // row 1 (mid1)
        float2 mL = lds2(p + BP + 1);
        float2 bL = lds2(p + BP + 3);
        float o0a = CO[sco], o0b = CO[sco + 1];
#pragma unroll
        for (int k = 0; k < 4; ++k) {
            const float* q = p + (2 * k + 2) * BP;             // mid2 row
            const float2 aH = lds2(q - 1);
            const float2 mH = lds2(q + 1);
            const float2 bH = lds2(q + 3);
            float2 aN = aH, bN = bH;
            float2 mN;
            if (k < 3) {                                       // next row full
                aN = lds2(q + BP - 1);
                mN = lds2(q + BP + 1);
                bN = lds2(q + BP + 3);
            } else {                                           // t3 only
                mN = lds2(q + BP + 1);
            }

            const float lap00 = 4.f * mL.x - aL.y - mL.y - mT.x - mH.x;
            const float lap01 = 4.f * mL.y - mL.x - bL.x - mT.y - mH.y;
            const float lap10 = 4.f * mH.x - aH.y - mH.y - mL.x - mN.x;
            const float lap11 = 4.f * mH.y - mH.x - bH.x - mL.y - mN.y;

            const float o1a = CO[sco + (k + 1) * COP];
            const float o1b = CO[sco + (k + 1) * COP + 1];

            const float r00 = fmaf(alpha, o0a * w4, bs * lap00);
            const float r01 = fmaf(alpha, fmaf(o0a, w5, o0b * w3), bs * lap01);
            const float r10 = fmaf(alpha, fmaf(o0a, w7, o1a * w1), bs * lap10);
            const float r11 = fmaf(alpha,
                fmaf(o0a, w8, fmaf(o0b, w6, fmaf(o1a, w2, o1b * w0))),
                bs * lap11);

            const int sm_ = sabm[k];
            if (K < 5) {
                const int n = (sm_ >> 18) & 63;
                float* ob = out + sio_base + (2 * k + 1) * BP + 1;
                if (n >= K) {                      // full interior quad
                    sts2(ob, r00, r01);
                    sts2(ob + BP, r10, r11);
                } else {
                    const int m = (sm_ >> 12) & 63;
                    if (m >= K) {                  // partial edge quad
                        const int a = sm_ & 63, b = (sm_ >> 6) & 63;
                        const bool ch = (b <= 41 - K), rh = (a <= 41 - K);
                        ob[0] = r00;
                        if (ch) ob[1] = r01;
                        if (rh) { ob[BP] = r10; if (ch) ob[BP + 1] = r11; }
                    }
                }
                fa[4 * k + 0] = fmaf(g, r00, fa[4 * k + 0]);
                fa[4 * k + 1] = fmaf(g, r01, fa[4 * k + 1]);
                fa[4 * k + 2] = fmaf(g, r10, fa[4 * k + 2]);
                fa[4 * k + 3] = fmaf(g, r11, fa[4 * k + 3]);
            } else {
                const int fm = (sm_ >> 24) & 15;
                if (fm) {
                    const int a = sm_ & 63, b = (sm_ >> 6) & 63;
                    float* fp = FA + (2 * a - 10) * FAP + (2 * b - 10);
                    const float v00 = fmaf(g, r00, fa[4 * k + 0]);
                    const float v01 = fmaf(g, r01, fa[4 * k + 1]);
                    const float v10 = fmaf(g, r10, fa[4 * k + 2]);
                    const float v11 = fmaf(g, r11, fa[4 * k + 3]);
                    const bool r0ok = fm & 1, r1ok = fm & 2;
                    const bool c0ok = fm & 4, c1ok = fm & 8;
                    if (r0ok) {
                        if (c0ok && c1ok) sts2(fp, v00, v01);
                        else { if (c0ok) fp[0] = v00; if (c1ok) fp[1] = v01; }
                    }
                    if (r1ok) {
                        if (c0ok && c1ok) sts2(fp + FAP, v10, v11);
                        else { if (c0ok) fp[FAP] = v10; if (c1ok) fp[FAP + 1] = v11; }
                    }
                }
            }
            mT = mH; aL = aN; mL = mN; bL = bN;
            o0a = o1a; o0b = o1b;
        }
    }
    __syncthreads();
}

// ---------------------------------------------------------------------------
// Mega kernel: 5 fused iterations + shrink epilogue
// ---------------------------------------------------------------------------
__global__ __launch_bounds__(NT, 2) void mega_kernel(
    const float* __restrict__ base0, const float* __restrict__ bX,
    const float* __restrict__ bY, const float* __restrict__ alpha_p,
    const float* __restrict__ beta0_p, const float* __restrict__ beta1_p,
    const float* __restrict__ sigma_p, const float* __restrict__ gamma,
    const float* __restrict__ w9, float* __restrict__ out)
{
    extern __shared__ __align__(16) float sm[];
    float* A  = sm;                 // 85*88
    float* B  = A + ASIZE;          // 85*88
    float* CO = B + ASIZE;          // 48*42 (incl. gated-garbage rows + dump)
    float* FA = B;                  // aliases B (dead after iter 4)

    const int tid = threadIdx.x;
    const int gx0 = blockIdx.x * CORE;
    const int gy0 = blockIdx.y * CORE;

    const float w0 = __ldg(&w9[0]), w1 = __ldg(&w9[1]), w2 = __ldg(&w9[2]);
    const float w3 = __ldg(&w9[3]), w4 = __ldg(&w9[4]), w5 = __ldg(&w9[5]);
    const float w6 = __ldg(&w9[6]), w7 = __ldg(&w9[7]), w8 = __ldg(&w9[8]);
    const float alpha = __ldg(alpha_p);
    const float bs = __ldg(beta0_p) + __ldg(sigma_p);

    // --- run precompute: vertical run of 4 slots (a0..a0+3, b) -------------
    int sio_base, sco, sabm[4];
    if (tid < NRUN) {
        const int rr = tid / 41;          // 0..10
        const int b  = tid - rr * 41 + 1; // 1..41
        const int a0 = 4 * rr + 1;        // 1,5,...,41
        sio_base = (2 * a0 - 1) * BP + (2 * b - 1);
        sco = (a0 - 1) * COP + (b - 1);
#pragma unroll
        for (int k = 0; k < 4; ++k) {
            const int a = a0 + k;         // up to 44; a>41 fully gated
            const int m = max(0, min(min(a, b), min(42 - a, 42 - b)));
            const int n = max(0, min(min(a, b), min(41 - a, 41 - b)));
            const int fm = ((a >= 5 && a <= 37) ? 1 : 0) |
                           ((a >= 5 && a <= 36) ? 2 : 0) |
                           ((b >= 5 && b <= 37) ? 4 : 0) |
                           ((b >= 5 && b <= 36) ? 8 : 0);
            sabm[k] = a | (b << 6) | (m << 12) | (n << 18) | (fm << 24);
        }
    } else {
        sio_base = SIO_IDLE; sco = CO_DUMP;
#pragma unroll
        for (int k = 0; k < 4; ++k) sabm[k] = 0;
    }

    // --- load 85x85 base0 patch ------------------------------------------
    const bool interior = (blockIdx.x >= 1) & (blockIdx.x <= gridDim.x - 2) &
                          (blockIdx.y >= 1) & (blockIdx.y <= gridDim.y - 2);
    if (interior) {
        const float* src = base0 + (gy0 - 10) * WW + (gx0 - 10);
        for (int idx = tid; idx < B0 * 43; idx += NT) {
            const int r = idx / 43;
            const int c2 = idx - r * 43;
            const float2 v = __ldg((const float2*)(src + r * WW + 2 * c2));
            *(float2*)(A + r * BP + 2 * c2) = v;
        }
    } else {
        for (int idx = tid; idx < B0 * B0; idx += NT) {
            const int r = idx / B0;
            const int c = idx - r * B0;
            A[r * BP + c] = __ldg(&base0[((gy0 - 10 + r) & MW) * WW +
                                         ((gx0 - 10 + c) & MW)]);
        }
    }
    __syncthreads();

    // --- f-reg init: fa = gamma[0] * base0 (quad values) -------------------
    float fa[16];
    const float g0 = __ldg(&gamma[0]);
#pragma unroll
    for (int k = 0; k < 4; ++k) {
        const float* pq = A + sio_base + (2 * k + 1) * BP + 1;
        const float2 u = lds2(pq);
        const float2 v = lds2(pq + BP);
        fa[4 * k + 0] = g0 * u.x;
        fa[4 * k + 1] = g0 * u.y;
        fa[4 * k + 2] = g0 * v.x;
        fa[4 * k + 3] = g0 * v.y;
    }

    iter_step<1>(A, B, CO, FA, sio_base, sco, sabm, fa,
                 w0, w1, w2, w3, w4, w5, w6, w7, w8, alpha, bs, __ldg(&gamma[1]));
    iter_step<2>(B, A, CO, FA, sio_base, sco, sabm, fa,
                 w0, w1, w2, w3, w4, w5, w6, w7, w8, alpha, bs, __ldg(&gamma[2]));
    iter_step<3>(A, B, CO, FA, sio_base, sco, sabm, fa,
                 w0, w1, w2, w3, w4, w5, w6, w7, w8, alpha, bs, __ldg(&gamma[3]));
    iter_step<4>(B, A, CO, FA, sio_base, sco, sabm, fa,
                 w0, w1, w2, w3, w4, w5, w6, w7, w8, alpha, bs, __ldg(&gamma[4]));
    // iter 5 reads A; writes f directly into FA (=B, dead since iter-4 sync)
    iter_step<5>(A, B, CO, FA, sio_base, sco, sabm, fa,
                 w0, w1, w2, w3, w4, w5, w6, w7, w8, alpha, bs, __ldg(&gamma[5]));

    // --- shrink / Bregman epilogue: 2 pixels per step ----------------------
    const float thr = __fdividef(__ldg(beta1_p), __ldg(sigma_p));
    for (int idx = tid; idx < 64 * 32; idx += NT) {
        const int r = idx >> 5;
        const int cp = idx & 31;
        const float* fr0 = FA + r * FAP + 2 * cp;
        const float2 f0 = lds2(fr0);
        const float fR = fr0[2];
        const float2 f1 = lds2(fr0 + FAP);
        const float dxf0 = f0.y - f0.x, dxf1 = fR - f0.y;
        const float dyf0 = f1.x - f0.x, dyf1 = f1.y - f0.y;
        const int ij = (gy0 + r) * WW + gx0 + 2 * cp;
        const float2 bx = __ldg((const float2*)(bX + ij));
        const float2 by = __ldg((const float2*)(bY + ij));
        const float px0 = dxf0 + bx.x, py0 = dyf0 + by.x;
        const float px1 = dxf1 + bx.y, py1 = dyf1 + by.y;
        const float n0 = sqrtf(fmaf(px0, px0, py0 * py0));
        const float n1 = sqrtf(fmaf(px1, px1, py1 * py1));
        const float sh0 = __fdividef(fmaxf(n0 - thr, 0.f), n0 + 1e-8f);
        const float sh1 = __fdividef(fmaxf(n1 - thr, 0.f), n1 + 1e-8f);
        const float dxn0 = px0 * sh0, dyn0 = py0 * sh0;
        const float dxn1 = px1 * sh1, dyn1 = py1 * sh1;
        *(float2*)(out + ij) = f0;
        *(float2*)(out + NPIX + ij) = make_float2(dxn0, dxn1);
        *(float2*)(out + 2 * NPIX + ij) = make_float2(dyn0, dyn1);
        *(float2*)(out + 3 * NPIX + ij) =
            make_float2(bx.x + dxf0 - dxn0, bx.y + dxf1 - dxn1);
        *(float2*)(out + 4 * NPIX + ij) =
            make_float2(by.x + dyf0 - dyn0, by.y + dyf1 - dyn1);
    }
}

static const int SMEM_BYTES = (2 * ASIZE + CO_SIZE) * 4;

extern "C" void kernel_launch(void* const* d_in, const int* in_sizes, int n_in,
                              void* d_out, int out_size)
{
    const float* STg   = (const float*)d_in[0];
    const float* dX    = (const float*)d_in[1];
    const float* dY    = (const float*)d_in[2];
    const float* bX    = (const float*)d_in[3];
    const float* bY    = (const float*)d_in[4];
    const float* alpha = (const float*)d_in[7];
    const float* beta0 = (const float*)d_in[8];
    const float* beta1 = (const float*)d_in[9];
    const float* sigma = (const float*)d_in[10];
    const float* gamma = (const float*)d_in[11];
    const float* w9    = (const float*)d_in[12];

    float* out = (float*)d_out;

    float* pB0;
    cudaGetSymbolAddress((void**)&pB0, g_base0);

    dim3 b1(32, 8), g1(WW / 64, HH / 8);
    stage0_kernel<<<g1, b1>>>(STg, dX, dY, bX, bY, alpha, sigma, w9, pB0);

    cudaFuncSetAttribute(mega_kernel,
                         cudaFuncAttributeMaxDynamicSharedMemorySize,
                         SMEM_BYTES);
    dim3 g2(WW / CORE, HH / CORE);
    mega_kernel<<<g2, NT, SMEM_BYTES>>>(pB0, bX, bY, alpha, beta0, beta1,
                                        sigma, gamma, w9, out);
}